// round 1
// baseline (speedup 1.0000x reference)
#include <cuda_runtime.h>
#include <math.h>

#define TOK 4096
#define DMODEL 1024
#define NH 16
#define DH 64
#define SEQ 2048

// ---------------- scratch (device globals: no allocation allowed) ----------
__device__ float g_xn[TOK * DMODEL];
__device__ float g_q[TOK * DMODEL];
__device__ float g_k[TOK * DMODEL];
__device__ float g_v[TOK * DMODEL];
__device__ float g_og[TOK * DMODEL];
__device__ float g_cs[TOK * 2];       // cos(phase), sin(phase) per token
__device__ float g_headT[TOK * NH];   // per-head resonance gate

// ---------------- kernel 1: LayerNorm + phase + gates + energy init --------
__global__ __launch_bounds__(256) void ln_phase_kernel(
    const float* __restrict__ x, const float* __restrict__ gamma,
    const float* __restrict__ beta, const float* __restrict__ Wp,
    const float* __restrict__ carrier, float* __restrict__ energy_slot)
{
    int row = blockIdx.x;
    int tid = threadIdx.x;
    __shared__ float red[16];
    __shared__ float bc[2];

    float4 v = ((const float4*)(x + (size_t)row * DMODEL))[tid];
    float s  = v.x + v.y + v.z + v.w;
    float ss = v.x * v.x + v.y * v.y + v.z * v.z + v.w * v.w;
#pragma unroll
    for (int o = 16; o; o >>= 1) {
        s  += __shfl_xor_sync(0xffffffffu, s, o);
        ss += __shfl_xor_sync(0xffffffffu, ss, o);
    }
    int warp = tid >> 5, lane = tid & 31;
    if (lane == 0) { red[warp] = s; red[warp + 8] = ss; }
    __syncthreads();
    if (tid == 0) {
        float a = 0.f, b = 0.f;
#pragma unroll
        for (int i = 0; i < 8; i++) { a += red[i]; b += red[i + 8]; }
        float mu  = a * (1.0f / DMODEL);
        float var = b * (1.0f / DMODEL) - mu * mu;
        bc[0] = mu;
        bc[1] = rsqrtf(var + 1e-5f);
    }
    __syncthreads();
    float mu = bc[0], rstd = bc[1];

    float4 g  = ((const float4*)gamma)[tid];
    float4 be = ((const float4*)beta)[tid];
    float4 xv;
    xv.x = (v.x - mu) * rstd * g.x + be.x;
    xv.y = (v.y - mu) * rstd * g.y + be.y;
    xv.z = (v.z - mu) * rstd * g.z + be.z;
    xv.w = (v.w - mu) * rstd * g.w + be.w;
    ((float4*)(g_xn + (size_t)row * DMODEL))[tid] = xv;

    float4 w = ((const float4*)Wp)[tid];
    float p = xv.x * w.x + xv.y * w.y + xv.z * w.z + xv.w * w.w;
#pragma unroll
    for (int o = 16; o; o >>= 1) p += __shfl_xor_sync(0xffffffffu, p, o);
    __syncthreads();                       // protect red reuse
    if (lane == 0) red[warp] = p;
    __syncthreads();
    if (tid == 0) {
        float a = 0.f;
#pragma unroll
        for (int i = 0; i < 8; i++) a += red[i];
        bc[0] = a;
    }
    __syncthreads();
    float phase = bc[0];
    if (tid == 0) {
        g_cs[2 * row]     = cosf(phase);
        g_cs[2 * row + 1] = sinf(phase);
    }
    if (tid < NH) {
        float c = cosf((phase - carrier[tid]) * 0.5f);
        g_headT[row * NH + tid] = c * c;
    }
    if (row == 0 && tid == 0) *energy_slot = 0.f;
}

// ---------------- SGEMM: C[m][n] = sum_k A[m][k]*W[n][k] (+ R[m][n]) -------
__global__ __launch_bounds__(256) void sgemm_wt(
    const float* __restrict__ A, const float* __restrict__ W,
    float* __restrict__ C, const float* __restrict__ R,
    int M, int N, int K)
{
    __shared__ float As[8][128];
    __shared__ float Bs[8][128];
    int tid = threadIdx.x;
    int bm = blockIdx.y * 128, bn = blockIdx.x * 128;
    int tx = tid & 15, ty = tid >> 4;
    int lrow = tid >> 1, lcol = (tid & 1) * 4;
    const float* Ap  = A + (size_t)(bm + lrow) * K + lcol;
    const float* Wpp = W + (size_t)(bn + lrow) * K + lcol;

    float acc[8][8];
#pragma unroll
    for (int i = 0; i < 8; i++)
#pragma unroll
        for (int j = 0; j < 8; j++) acc[i][j] = 0.f;

    for (int k0 = 0; k0 < K; k0 += 8) {
        float4 av = *(const float4*)(Ap + k0);
        float4 bv = *(const float4*)(Wpp + k0);
        __syncthreads();
        As[lcol + 0][lrow] = av.x; As[lcol + 1][lrow] = av.y;
        As[lcol + 2][lrow] = av.z; As[lcol + 3][lrow] = av.w;
        Bs[lcol + 0][lrow] = bv.x; Bs[lcol + 1][lrow] = bv.y;
        Bs[lcol + 2][lrow] = bv.z; Bs[lcol + 3][lrow] = bv.w;
        __syncthreads();
#pragma unroll
        for (int kk = 0; kk < 8; kk++) {
            float a[8], b[8];
            float4 t0 = *(const float4*)&As[kk][ty * 4];
            float4 t1 = *(const float4*)&As[kk][64 + ty * 4];
            a[0] = t0.x; a[1] = t0.y; a[2] = t0.z; a[3] = t0.w;
            a[4] = t1.x; a[5] = t1.y; a[6] = t1.z; a[7] = t1.w;
            float4 u0 = *(const float4*)&Bs[kk][tx * 4];
            float4 u1 = *(const float4*)&Bs[kk][64 + tx * 4];
            b[0] = u0.x; b[1] = u0.y; b[2] = u0.z; b[3] = u0.w;
            b[4] = u1.x; b[5] = u1.y; b[6] = u1.z; b[7] = u1.w;
#pragma unroll
            for (int i = 0; i < 8; i++)
#pragma unroll
                for (int j = 0; j < 8; j++)
                    acc[i][j] += a[i] * b[j];
        }
    }

#pragma unroll
    for (int i = 0; i < 8; i++) {
        int rr = (i < 4) ? (ty * 4 + i) : (64 + ty * 4 + i - 4);
        size_t base = (size_t)(bm + rr) * N + bn;
        float4 c0 = make_float4(acc[i][0], acc[i][1], acc[i][2], acc[i][3]);
        float4 c1 = make_float4(acc[i][4], acc[i][5], acc[i][6], acc[i][7]);
        if (R) {
            float4 r0 = *(const float4*)(R + base + tx * 4);
            float4 r1 = *(const float4*)(R + base + 64 + tx * 4);
            c0.x += r0.x; c0.y += r0.y; c0.z += r0.z; c0.w += r0.w;
            c1.x += r1.x; c1.y += r1.y; c1.z += r1.z; c1.w += r1.w;
        }
        *(float4*)(C + base + tx * 4) = c0;
        *(float4*)(C + base + 64 + tx * 4) = c1;
    }
}

// ---------------- flash attention + resonance + gating + energy ------------
// grid (SEQ/64, B*NH), 256 threads. Dynamic smem:
//   Qs[64][68], Ks[64][68], Vt[64][68] (V transposed), Ps[64][68], csq[64][2], csk[64][2]
__global__ __launch_bounds__(256) void attn_kernel(
    const float* __restrict__ lam_ptr, float* __restrict__ energy)
{
    extern __shared__ float sm[];
    float* Qs  = sm;
    float* Ks  = sm + 4352;
    float* Vt  = sm + 2 * 4352;
    float* Ps  = sm + 3 * 4352;
    float* csq = sm + 4 * 4352;
    float* csk = csq + 128;

    int tid = threadIdx.x;
    int bh = blockIdx.y;
    int b = bh >> 4, h = bh & (NH - 1);
    int q0 = blockIdx.x * 64;
    int T0 = b * SEQ;
    float lamh = 0.5f * (*lam_ptr);
    const float scale = 0.125f;  // 1/sqrt(64)

    int lrow = tid >> 4;   // 0..15
    int ld4  = tid & 15;   // float4 column

    // load Q tile (pre-scaled)
#pragma unroll
    for (int it = 0; it < 4; it++) {
        int rw = lrow + it * 16;
        float4 qv = *(const float4*)(g_q + (size_t)(T0 + q0 + rw) * DMODEL + h * DH + ld4 * 4);
        qv.x *= scale; qv.y *= scale; qv.z *= scale; qv.w *= scale;
        *(float4*)&Qs[rw * 68 + ld4 * 4] = qv;
    }
    if (tid < 64) {
        csq[tid * 2]     = g_cs[2 * (T0 + q0 + tid)];
        csq[tid * 2 + 1] = g_cs[2 * (T0 + q0 + tid) + 1];
    }

    int r  = tid >> 2;   // row 0..63 (4 threads per row)
    int c4 = tid & 3;    // column phase: thread owns cols c4 + 4*cc
    float m_run = -1e30f, l_part = 0.f;
    float acc[16];
#pragma unroll
    for (int i = 0; i < 16; i++) acc[i] = 0.f;

    for (int kt = 0; kt < SEQ / 64; kt++) {
        int k0 = kt * 64;
        __syncthreads();  // previous iteration's tile reads complete
#pragma unroll
        for (int it = 0; it < 4; it++) {
            int rw = lrow + it * 16;
            size_t gi = (size_t)(T0 + k0 + rw) * DMODEL + h * DH + ld4 * 4;
            float4 kv = *(const float4*)(g_k + gi);
            *(float4*)&Ks[rw * 68 + ld4 * 4] = kv;
            float4 vv = *(const float4*)(g_v + gi);
            Vt[(ld4 * 4 + 0) * 68 + rw] = vv.x;
            Vt[(ld4 * 4 + 1) * 68 + rw] = vv.y;
            Vt[(ld4 * 4 + 2) * 68 + rw] = vv.z;
            Vt[(ld4 * 4 + 3) * 68 + rw] = vv.w;
        }
        if (tid < 64) {
            csk[tid * 2]     = g_cs[2 * (T0 + k0 + tid)];
            csk[tid * 2 + 1] = g_cs[2 * (T0 + k0 + tid) + 1];
        }
        __syncthreads();

        float qc = csq[r * 2], qs = csq[r * 2 + 1];
        float s[16];
#pragma unroll
        for (int cc = 0; cc < 16; cc++) {
            int c = c4 + cc * 4;
            s[cc] = lamh + lamh * (qc * csk[c * 2] + qs * csk[c * 2 + 1]);
        }
#pragma unroll
        for (int k4 = 0; k4 < 16; k4++) {
            float4 qv = *(const float4*)&Qs[r * 68 + k4 * 4];
#pragma unroll
            for (int cc = 0; cc < 16; cc++) {
                int c = c4 + cc * 4;
                float4 kv = *(const float4*)&Ks[c * 68 + k4 * 4];
                s[cc] += qv.x * kv.x + qv.y * kv.y + qv.z * kv.z + qv.w * kv.w;
            }
        }

        // online softmax
        float mx = s[0];
#pragma unroll
        for (int cc = 1; cc < 16; cc++) mx = fmaxf(mx, s[cc]);
        mx = fmaxf(mx, __shfl_xor_sync(0xffffffffu, mx, 1, 4));
        mx = fmaxf(mx, __shfl_xor_sync(0xffffffffu, mx, 2, 4));
        float m_new = fmaxf(m_run, mx);
        float alpha = __expf(m_run - m_new);
        m_run = m_new;
        l_part *= alpha;
#pragma unroll
        for (int i = 0; i < 16; i++) acc[i] *= alpha;
        float lsum = 0.f;
#pragma unroll
        for (int cc = 0; cc < 16; cc++) {
            float p = __expf(s[cc] - m_new);
            lsum += p;
            Ps[r * 68 + c4 + cc * 4] = p;
        }
        l_part += lsum;
        __syncwarp();  // Ps for row r produced by 4 lanes of this warp

        // PV: acc[dd] += sum_j P[r][j] * V[j][d],  d = c4 + 4*dd
#pragma unroll
        for (int j4 = 0; j4 < 16; j4++) {
            float4 p4 = *(const float4*)&Ps[r * 68 + j4 * 4];
#pragma unroll
            for (int dd = 0; dd < 16; dd++) {
                int d = c4 + dd * 4;
                float4 v4 = *(const float4*)&Vt[d * 68 + j4 * 4];
                acc[dd] += p4.x * v4.x + p4.y * v4.y + p4.z * v4.z + p4.w * v4.w;
            }
        }
    }

    float l = l_part;
    l += __shfl_xor_sync(0xffffffffu, l, 1, 4);
    l += __shfl_xor_sync(0xffffffffu, l, 2, 4);
    float gate = g_headT[(T0 + q0 + r) * NH + h];
    float inv = gate / l;
    float esum = 0.f;
#pragma unroll
    for (int dd = 0; dd < 16; dd++) {
        float o = acc[dd] * inv;
        esum += fabsf(o);
        g_og[(size_t)(T0 + q0 + r) * DMODEL + h * DH + c4 + dd * 4] = o;
    }
#pragma unroll
    for (int o = 16; o; o >>= 1) esum += __shfl_xor_sync(0xffffffffu, esum, o);
    __shared__ float wsum[8];
    if ((tid & 31) == 0) wsum[tid >> 5] = esum;
    __syncthreads();
    if (tid == 0) {
        float t = 0.f;
#pragma unroll
        for (int i = 0; i < 8; i++) t += wsum[i];
        atomicAdd(energy, t);
    }
}

// ---------------- launch ---------------------------------------------------
extern "C" void kernel_launch(void* const* d_in, const int* in_sizes, int n_in,
                              void* d_out, int out_size)
{
    const float* x       = (const float*)d_in[0];
    const float* Wq      = (const float*)d_in[1];
    const float* Wk      = (const float*)d_in[2];
    const float* Wv      = (const float*)d_in[3];
    const float* Wo      = (const float*)d_in[4];
    const float* Wp      = (const float*)d_in[5];
    const float* gamma   = (const float*)d_in[6];
    const float* beta    = (const float*)d_in[7];
    const float* carrier = (const float*)d_in[8];
    const float* lam     = (const float*)d_in[9];

    float* out    = (float*)d_out;
    float* energy = out + (out_size - 1);

    float *p_xn, *p_q, *p_k, *p_v, *p_og;
    cudaGetSymbolAddress((void**)&p_xn, g_xn);
    cudaGetSymbolAddress((void**)&p_q,  g_q);
    cudaGetSymbolAddress((void**)&p_k,  g_k);
    cudaGetSymbolAddress((void**)&p_v,  g_v);
    cudaGetSymbolAddress((void**)&p_og, g_og);

    ln_phase_kernel<<<TOK, 256>>>(x, gamma, beta, Wp, carrier, energy);

    dim3 gg(DMODEL / 128, TOK / 128);
    sgemm_wt<<<gg, 256>>>(p_xn, Wq, p_q, nullptr, TOK, DMODEL, DMODEL);
    sgemm_wt<<<gg, 256>>>(p_xn, Wk, p_k, nullptr, TOK, DMODEL, DMODEL);
    sgemm_wt<<<gg, 256>>>(p_xn, Wv, p_v, nullptr, TOK, DMODEL, DMODEL);

    size_t shm = (size_t)(4 * 4352 + 256) * sizeof(float);  // 70656 B
    cudaFuncSetAttribute(attn_kernel, cudaFuncAttributeMaxDynamicSharedMemorySize, (int)shm);
    attn_kernel<<<dim3(SEQ / 64, 2 * NH), 256, shm>>>(lam, energy);

    sgemm_wt<<<gg, 256>>>(p_og, Wo, out, x, TOK, DMODEL, DMODEL);
}

// round 2
// speedup vs baseline: 1.0554x; 1.0554x over previous
#include <cuda_runtime.h>
#include <math.h>

#define TOK 4096
#define DMODEL 1024
#define NH 16
#define DH 64
#define SEQ 2048

// ---------------- scratch (device globals: no allocation allowed) ----------
__device__ float g_xn[TOK * DMODEL];
__device__ float g_q[TOK * DMODEL];
__device__ float g_k[TOK * DMODEL];
__device__ float g_v[TOK * DMODEL];
__device__ float g_og[TOK * DMODEL];
__device__ float g_cs[TOK * 2];       // cos(phase), sin(phase) per token
__device__ float g_headT[TOK * NH];   // per-head resonance gate

// ---------------- kernel 1: LayerNorm + phase + gates + energy init --------
__global__ __launch_bounds__(256) void ln_phase_kernel(
    const float* __restrict__ x, const float* __restrict__ gamma,
    const float* __restrict__ beta, const float* __restrict__ Wp,
    const float* __restrict__ carrier, float* __restrict__ energy_slot)
{
    int row = blockIdx.x;
    int tid = threadIdx.x;
    __shared__ float red[16];
    __shared__ float bc[2];

    float4 v = ((const float4*)(x + (size_t)row * DMODEL))[tid];
    float s  = v.x + v.y + v.z + v.w;
    float ss = v.x * v.x + v.y * v.y + v.z * v.z + v.w * v.w;
#pragma unroll
    for (int o = 16; o; o >>= 1) {
        s  += __shfl_xor_sync(0xffffffffu, s, o);
        ss += __shfl_xor_sync(0xffffffffu, ss, o);
    }
    int warp = tid >> 5, lane = tid & 31;
    if (lane == 0) { red[warp] = s; red[warp + 8] = ss; }
    __syncthreads();
    if (tid == 0) {
        float a = 0.f, b = 0.f;
#pragma unroll
        for (int i = 0; i < 8; i++) { a += red[i]; b += red[i + 8]; }
        float mu  = a * (1.0f / DMODEL);
        float var = b * (1.0f / DMODEL) - mu * mu;
        bc[0] = mu;
        bc[1] = rsqrtf(var + 1e-5f);
    }
    __syncthreads();
    float mu = bc[0], rstd = bc[1];

    float4 g  = ((const float4*)gamma)[tid];
    float4 be = ((const float4*)beta)[tid];
    float4 xv;
    xv.x = (v.x - mu) * rstd * g.x + be.x;
    xv.y = (v.y - mu) * rstd * g.y + be.y;
    xv.z = (v.z - mu) * rstd * g.z + be.z;
    xv.w = (v.w - mu) * rstd * g.w + be.w;
    ((float4*)(g_xn + (size_t)row * DMODEL))[tid] = xv;

    float4 w = ((const float4*)Wp)[tid];
    float p = xv.x * w.x + xv.y * w.y + xv.z * w.z + xv.w * w.w;
#pragma unroll
    for (int o = 16; o; o >>= 1) p += __shfl_xor_sync(0xffffffffu, p, o);
    __syncthreads();                       // protect red reuse
    if (lane == 0) red[warp] = p;
    __syncthreads();
    if (tid == 0) {
        float a = 0.f;
#pragma unroll
        for (int i = 0; i < 8; i++) a += red[i];
        bc[0] = a;
    }
    __syncthreads();
    float phase = bc[0];
    if (tid == 0) {
        g_cs[2 * row]     = cosf(phase);
        g_cs[2 * row + 1] = sinf(phase);
    }
    if (tid < NH) {
        float c = cosf((phase - carrier[tid]) * 0.5f);
        g_headT[row * NH + tid] = c * c;
    }
    if (row == 0 && tid == 0) *energy_slot = 0.f;
}

// ---------------- SGEMM: C[m][n] = sum_k A[m][k]*W[n][k] (+ R[m][n]) -------
__global__ __launch_bounds__(256) void sgemm_wt(
    const float* __restrict__ A, const float* __restrict__ W,
    float* __restrict__ C, const float* __restrict__ R,
    int M, int N, int K)
{
    __shared__ float As[8][128];
    __shared__ float Bs[8][128];
    int tid = threadIdx.x;
    int bm = blockIdx.y * 128, bn = blockIdx.x * 128;
    int tx = tid & 15, ty = tid >> 4;
    int lrow = tid >> 1, lcol = (tid & 1) * 4;
    const float* Ap  = A + (size_t)(bm + lrow) * K + lcol;
    const float* Wpp = W + (size_t)(bn + lrow) * K + lcol;

    float acc[8][8];
#pragma unroll
    for (int i = 0; i < 8; i++)
#pragma unroll
        for (int j = 0; j < 8; j++) acc[i][j] = 0.f;

    for (int k0 = 0; k0 < K; k0 += 8) {
        float4 av = *(const float4*)(Ap + k0);
        float4 bv = *(const float4*)(Wpp + k0);
        __syncthreads();
        As[lcol + 0][lrow] = av.x; As[lcol + 1][lrow] = av.y;
        As[lcol + 2][lrow] = av.z; As[lcol + 3][lrow] = av.w;
        Bs[lcol + 0][lrow] = bv.x; Bs[lcol + 1][lrow] = bv.y;
        Bs[lcol + 2][lrow] = bv.z; Bs[lcol + 3][lrow] = bv.w;
        __syncthreads();
#pragma unroll
        for (int kk = 0; kk < 8; kk++) {
            float a[8], b[8];
            float4 t0 = *(const float4*)&As[kk][ty * 4];
            float4 t1 = *(const float4*)&As[kk][64 + ty * 4];
            a[0] = t0.x; a[1] = t0.y; a[2] = t0.z; a[3] = t0.w;
            a[4] = t1.x; a[5] = t1.y; a[6] = t1.z; a[7] = t1.w;
            float4 u0 = *(const float4*)&Bs[kk][tx * 4];
            float4 u1 = *(const float4*)&Bs[kk][64 + tx * 4];
            b[0] = u0.x; b[1] = u0.y; b[2] = u0.z; b[3] = u0.w;
            b[4] = u1.x; b[5] = u1.y; b[6] = u1.z; b[7] = u1.w;
#pragma unroll
            for (int i = 0; i < 8; i++)
#pragma unroll
                for (int j = 0; j < 8; j++)
                    acc[i][j] += a[i] * b[j];
        }
    }

#pragma unroll
    for (int i = 0; i < 8; i++) {
        int rr = (i < 4) ? (ty * 4 + i) : (64 + ty * 4 + i - 4);
        size_t base = (size_t)(bm + rr) * N + bn;
        float4 c0 = make_float4(acc[i][0], acc[i][1], acc[i][2], acc[i][3]);
        float4 c1 = make_float4(acc[i][4], acc[i][5], acc[i][6], acc[i][7]);
        if (R) {
            float4 r0 = *(const float4*)(R + base + tx * 4);
            float4 r1 = *(const float4*)(R + base + 64 + tx * 4);
            c0.x += r0.x; c0.y += r0.y; c0.z += r0.z; c0.w += r0.w;
            c1.x += r1.x; c1.y += r1.y; c1.z += r1.z; c1.w += r1.w;
        }
        *(float4*)(C + base + tx * 4) = c0;
        *(float4*)(C + base + 64 + tx * 4) = c1;
    }
}

// ---------------- flash attention + resonance + gating + energy ------------
// grid (SEQ/64, B*NH), 256 threads. Dynamic smem:
//   Qs[64][68], Ks[64][68], Vt[64][68] (V transposed), Ps[64][68], csq[64][2], csk[64][2]
__global__ __launch_bounds__(256) void attn_kernel(
    const float* __restrict__ lam_ptr, float* __restrict__ energy)
{
    extern __shared__ float sm[];
    float* Qs  = sm;
    float* Ks  = sm + 4352;
    float* Vt  = sm + 2 * 4352;
    float* Ps  = sm + 3 * 4352;
    float* csq = sm + 4 * 4352;
    float* csk = csq + 128;

    int tid = threadIdx.x;
    int bh = blockIdx.y;
    int b = bh >> 4, h = bh & (NH - 1);
    int q0 = blockIdx.x * 64;
    int T0 = b * SEQ;
    float lamh = 0.5f * (*lam_ptr);
    const float scale = 0.125f;  // 1/sqrt(64)

    int lrow = tid >> 4;   // 0..15
    int ld4  = tid & 15;   // float4 column

    // load Q tile (pre-scaled)
#pragma unroll
    for (int it = 0; it < 4; it++) {
        int rw = lrow + it * 16;
        float4 qv = *(const float4*)(g_q + (size_t)(T0 + q0 + rw) * DMODEL + h * DH + ld4 * 4);
        qv.x *= scale; qv.y *= scale; qv.z *= scale; qv.w *= scale;
        *(float4*)&Qs[rw * 68 + ld4 * 4] = qv;
    }
    if (tid < 64) {
        csq[tid * 2]     = g_cs[2 * (T0 + q0 + tid)];
        csq[tid * 2 + 1] = g_cs[2 * (T0 + q0 + tid) + 1];
    }

    int r  = tid >> 2;   // row 0..63 (4 threads per row)
    int c4 = tid & 3;    // column phase: thread owns cols c4 + 4*cc
    float m_run = -1e30f, l_part = 0.f;
    float acc[16];
#pragma unroll
    for (int i = 0; i < 16; i++) acc[i] = 0.f;

    for (int kt = 0; kt < SEQ / 64; kt++) {
        int k0 = kt * 64;
        __syncthreads();  // previous iteration's tile reads complete
#pragma unroll
        for (int it = 0; it < 4; it++) {
            int rw = lrow + it * 16;
            size_t gi = (size_t)(T0 + k0 + rw) * DMODEL + h * DH + ld4 * 4;
            float4 kv = *(const float4*)(g_k + gi);
            *(float4*)&Ks[rw * 68 + ld4 * 4] = kv;
            float4 vv = *(const float4*)(g_v + gi);
            Vt[(ld4 * 4 + 0) * 68 + rw] = vv.x;
            Vt[(ld4 * 4 + 1) * 68 + rw] = vv.y;
            Vt[(ld4 * 4 + 2) * 68 + rw] = vv.z;
            Vt[(ld4 * 4 + 3) * 68 + rw] = vv.w;
        }
        if (tid < 64) {
            csk[tid * 2]     = g_cs[2 * (T0 + k0 + tid)];
            csk[tid * 2 + 1] = g_cs[2 * (T0 + k0 + tid) + 1];
        }
        __syncthreads();

        float qc = csq[r * 2], qs = csq[r * 2 + 1];
        float s[16];
#pragma unroll
        for (int cc = 0; cc < 16; cc++) {
            int c = c4 + cc * 4;
            s[cc] = lamh + lamh * (qc * csk[c * 2] + qs * csk[c * 2 + 1]);
        }
#pragma unroll
        for (int k4 = 0; k4 < 16; k4++) {
            float4 qv = *(const float4*)&Qs[r * 68 + k4 * 4];
#pragma unroll
            for (int cc = 0; cc < 16; cc++) {
                int c = c4 + cc * 4;
                float4 kv = *(const float4*)&Ks[c * 68 + k4 * 4];
                s[cc] += qv.x * kv.x + qv.y * kv.y + qv.z * kv.z + qv.w * kv.w;
            }
        }

        // online softmax
        float mx = s[0];
#pragma unroll
        for (int cc = 1; cc < 16; cc++) mx = fmaxf(mx, s[cc]);
        mx = fmaxf(mx, __shfl_xor_sync(0xffffffffu, mx, 1, 4));
        mx = fmaxf(mx, __shfl_xor_sync(0xffffffffu, mx, 2, 4));
        float m_new = fmaxf(m_run, mx);
        float alpha = __expf(m_run - m_new);
        m_run = m_new;
        l_part *= alpha;
#pragma unroll
        for (int i = 0; i < 16; i++) acc[i] *= alpha;
        float lsum = 0.f;
#pragma unroll
        for (int cc = 0; cc < 16; cc++) {
            float p = __expf(s[cc] - m_new);
            lsum += p;
            Ps[r * 68 + c4 + cc * 4] = p;
        }
        l_part += lsum;
        __syncwarp();  // Ps for row r produced by 4 lanes of this warp

        // PV: acc[dd] += sum_j P[r][j] * V[j][d],  d = c4 + 4*dd
#pragma unroll
        for (int j4 = 0; j4 < 16; j4++) {
            float4 p4 = *(const float4*)&Ps[r * 68 + j4 * 4];
#pragma unroll
            for (int dd = 0; dd < 16; dd++) {
                int d = c4 + dd * 4;
                float4 v4 = *(const float4*)&Vt[d * 68 + j4 * 4];
                acc[dd] += p4.x * v4.x + p4.y * v4.y + p4.z * v4.z + p4.w * v4.w;
            }
        }
    }

    float l = l_part;
    l += __shfl_xor_sync(0xffffffffu, l, 1, 4);
    l += __shfl_xor_sync(0xffffffffu, l, 2, 4);
    float gate = g_headT[(T0 + q0 + r) * NH + h];
    float inv = gate / l;
    float esum = 0.f;
#pragma unroll
    for (int dd = 0; dd < 16; dd++) {
        float o = acc[dd] * inv;
        esum += fabsf(o);
        g_og[(size_t)(T0 + q0 + r) * DMODEL + h * DH + c4 + dd * 4] = o;
    }
#pragma unroll
    for (int o = 16; o; o >>= 1) esum += __shfl_xor_sync(0xffffffffu, esum, o);
    __shared__ float wsum[8];
    if ((tid & 31) == 0) wsum[tid >> 5] = esum;
    __syncthreads();
    if (tid == 0) {
        float t = 0.f;
#pragma unroll
        for (int i = 0; i < 8; i++) t += wsum[i];
        atomicAdd(energy, t);
    }
}

// ---------------- launch ---------------------------------------------------
extern "C" void kernel_launch(void* const* d_in, const int* in_sizes, int n_in,
                              void* d_out, int out_size)
{
    const float* x       = (const float*)d_in[0];
    const float* Wq      = (const float*)d_in[1];
    const float* Wk      = (const float*)d_in[2];
    const float* Wv      = (const float*)d_in[3];
    const float* Wo      = (const float*)d_in[4];
    const float* Wp      = (const float*)d_in[5];
    const float* gamma   = (const float*)d_in[6];
    const float* beta    = (const float*)d_in[7];
    const float* carrier = (const float*)d_in[8];
    const float* lam     = (const float*)d_in[9];

    float* out    = (float*)d_out;
    float* energy = out + (out_size - 1);

    float *p_xn, *p_q, *p_k, *p_v, *p_og;
    cudaGetSymbolAddress((void**)&p_xn, g_xn);
    cudaGetSymbolAddress((void**)&p_q,  g_q);
    cudaGetSymbolAddress((void**)&p_k,  g_k);
    cudaGetSymbolAddress((void**)&p_v,  g_v);
    cudaGetSymbolAddress((void**)&p_og, g_og);

    ln_phase_kernel<<<TOK, 256>>>(x, gamma, beta, Wp, carrier, energy);

    dim3 gg(DMODEL / 128, TOK / 128);
    sgemm_wt<<<gg, 256>>>(p_xn, Wq, p_q, nullptr, TOK, DMODEL, DMODEL);
    sgemm_wt<<<gg, 256>>>(p_xn, Wk, p_k, nullptr, TOK, DMODEL, DMODEL);
    sgemm_wt<<<gg, 256>>>(p_xn, Wv, p_v, nullptr, TOK, DMODEL, DMODEL);

    size_t shm = (size_t)(4 * 4352 + 256) * sizeof(float);  // 70656 B
    cudaFuncSetAttribute(attn_kernel, cudaFuncAttributeMaxDynamicSharedMemorySize, (int)shm);
    attn_kernel<<<dim3(SEQ / 64, 2 * NH), 256, shm>>>(lam, energy);

    sgemm_wt<<<gg, 256>>>(p_og, Wo, out, x, TOK, DMODEL, DMODEL);
}

// round 4
// speedup vs baseline: 10.2301x; 9.6928x over previous
#include <cuda_runtime.h>
#include <cuda_bf16.h>
#include <math.h>
#include <stdint.h>

#define TOK 4096
#define DM 1024
#define NH 16
#define DH 64
#define SEQ 2048

// ---------------- scratch (device globals) ---------------------------------
__device__ __nv_bfloat16 g_xnb[TOK * DM];
__device__ __nv_bfloat16 g_qb[TOK * DM];
__device__ __nv_bfloat16 g_kb[TOK * DM];
__device__ __nv_bfloat16 g_vb[TOK * DM];
__device__ __nv_bfloat16 g_ogb[TOK * DM];
__device__ __nv_bfloat16 g_wb[4][DM * DM];     // Wq,Wk,Wv,Wo bf16
__device__ float2 g_cs2[TOK];
__device__ float g_headT[TOK * NH];

// ---------------- helpers ---------------------------------------------------
__device__ __forceinline__ uint32_t s2u(const void* p) {
    uint32_t a;
    asm("{ .reg .u64 t; cvta.to.shared.u64 t, %1; cvt.u32.u64 %0, t; }"
        : "=r"(a) : "l"(p));
    return a;
}
__device__ __forceinline__ uint32_t pkbf(float a, float b) {
    __nv_bfloat162 h = __floats2bfloat162_rn(a, b);
    return *reinterpret_cast<uint32_t*>(&h);
}
#define SW(o) ((uint32_t)(o) ^ ((((uint32_t)(o)) >> 3) & 0x70))

#define CPA(dst, src) asm volatile( \
    "cp.async.cg.shared.global [%0], [%1], 16;" :: "r"(dst), "l"(src))
#define CPCOMMIT() asm volatile("cp.async.commit_group;" ::: "memory")
#define CPWAIT1() asm volatile("cp.async.wait_group 1;" ::: "memory")
#define CPWAIT0() asm volatile("cp.async.wait_group 0;" ::: "memory")

#define LDSM4(r, a) asm volatile( \
    "ldmatrix.sync.aligned.m8n8.x4.shared.b16 {%0,%1,%2,%3}, [%4];" \
    : "=r"((r)[0]), "=r"((r)[1]), "=r"((r)[2]), "=r"((r)[3]) : "r"(a))
#define LDSM4T(r, a) asm volatile( \
    "ldmatrix.sync.aligned.m8n8.x4.trans.shared.b16 {%0,%1,%2,%3}, [%4];" \
    : "=r"((r)[0]), "=r"((r)[1]), "=r"((r)[2]), "=r"((r)[3]) : "r"(a))

__device__ __forceinline__ void mma16816(float* d, const uint32_t* a,
                                         uint32_t b0, uint32_t b1) {
    asm volatile(
        "mma.sync.aligned.m16n8k16.row.col.f32.bf16.bf16.f32 "
        "{%0,%1,%2,%3}, {%4,%5,%6,%7}, {%8,%9}, {%0,%1,%2,%3};"
        : "+f"(d[0]), "+f"(d[1]), "+f"(d[2]), "+f"(d[3])
        : "r"(a[0]), "r"(a[1]), "r"(a[2]), "r"(a[3]), "r"(b0), "r"(b1));
}

// ---------------- kernel 1: LayerNorm + phase + gates ----------------------
__global__ __launch_bounds__(256) void ln_phase_kernel(
    const float* __restrict__ x, const float* __restrict__ gamma,
    const float* __restrict__ beta, const float* __restrict__ Wp,
    const float* __restrict__ carrier, float* __restrict__ energy_slot)
{
    int row = blockIdx.x;
    int tid = threadIdx.x;
    __shared__ float red[16];
    __shared__ float bc[2];

    float4 v = ((const float4*)(x + (size_t)row * DM))[tid];
    float s  = v.x + v.y + v.z + v.w;
    float ss = v.x * v.x + v.y * v.y + v.z * v.z + v.w * v.w;
#pragma unroll
    for (int o = 16; o; o >>= 1) {
        s  += __shfl_xor_sync(0xffffffffu, s, o);
        ss += __shfl_xor_sync(0xffffffffu, ss, o);
    }
    int warp = tid >> 5, lane = tid & 31;
    if (lane == 0) { red[warp] = s; red[warp + 8] = ss; }
    __syncthreads();
    if (tid == 0) {
        float a = 0.f, b = 0.f;
#pragma unroll
        for (int i = 0; i < 8; i++) { a += red[i]; b += red[i + 8]; }
        float mu  = a * (1.0f / DM);
        float var = b * (1.0f / DM) - mu * mu;
        bc[0] = mu; bc[1] = rsqrtf(var + 1e-5f);
    }
    __syncthreads();
    float mu = bc[0], rstd = bc[1];

    float4 g  = ((const float4*)gamma)[tid];
    float4 be = ((const float4*)beta)[tid];
    float4 xv;
    xv.x = (v.x - mu) * rstd * g.x + be.x;
    xv.y = (v.y - mu) * rstd * g.y + be.y;
    xv.z = (v.z - mu) * rstd * g.z + be.z;
    xv.w = (v.w - mu) * rstd * g.w + be.w;
    uint32_t* dst = (uint32_t*)(g_xnb + (size_t)row * DM + tid * 4);
    dst[0] = pkbf(xv.x, xv.y);
    dst[1] = pkbf(xv.z, xv.w);

    float4 w = ((const float4*)Wp)[tid];
    float p = xv.x * w.x + xv.y * w.y + xv.z * w.z + xv.w * w.w;
#pragma unroll
    for (int o = 16; o; o >>= 1) p += __shfl_xor_sync(0xffffffffu, p, o);
    __syncthreads();
    if (lane == 0) red[warp] = p;
    __syncthreads();
    if (tid == 0) {
        float a = 0.f;
#pragma unroll
        for (int i = 0; i < 8; i++) a += red[i];
        bc[0] = a;
    }
    __syncthreads();
    float phase = bc[0];
    if (tid == 0) g_cs2[row] = make_float2(cosf(phase), sinf(phase));
    if (tid < NH) {
        float c = cosf((phase - carrier[tid]) * 0.5f);
        g_headT[row * NH + tid] = c * c;
    }
    if (row == 0 && tid == 0) *energy_slot = 0.f;
}

// ---------------- kernel 2: weight fp32->bf16 ------------------------------
__global__ __launch_bounds__(256) void wconv_kernel(
    const float* __restrict__ W0, const float* __restrict__ W1,
    const float* __restrict__ W2, const float* __restrict__ W3)
{
    int gid = blockIdx.x * 256 + threadIdx.x;
    int a = gid >> 18, r = gid & 0x3FFFF;
    const float* src = (a == 0) ? W0 : (a == 1) ? W1 : (a == 2) ? W2 : W3;
    float4 v = ((const float4*)src)[r];
    uint32_t* d = (uint32_t*)(&g_wb[a][0] + (size_t)r * 4);
    d[0] = pkbf(v.x, v.y);
    d[1] = pkbf(v.z, v.w);
}

// ---------------- kernel 3: HMMA GEMM  C = A @ W^T -------------------------
// mode 0: Q (scale 0.125)  1: K  2: V  3: out fp32 + residual
__global__ __launch_bounds__(256) void gemm_hmma(
    const float* __restrict__ xres, float* __restrict__ outf, int modeParam)
{
    extern __shared__ char smraw[];
    uint32_t sb = s2u(smraw);
    int tid = threadIdx.x, lane = tid & 31, w = tid >> 5;
    int mode = (modeParam >= 0) ? modeParam : blockIdx.z;
    const __nv_bfloat16* A = (mode == 3) ? g_ogb : g_xnb;
    const __nv_bfloat16* W = g_wb[mode];
    int bm = blockIdx.y * 128, bn = blockIdx.x * 128;
    uint32_t As[2] = {sb, sb + 16384};
    uint32_t Ws[2] = {sb + 32768, sb + 49152};

    float acc[16][4];
#pragma unroll
    for (int j = 0; j < 16; j++)
#pragma unroll
        for (int q = 0; q < 4; q++) acc[j][q] = 0.f;

    // prologue load chunk 0
    {
#pragma unroll
        for (int it = 0; it < 4; it++) {
            int i = tid + it * 256;
            int row = i >> 3, ch = i & 7;
            uint32_t so = SW(row * 128 + ch * 16);
            CPA(As[0] + so, A + (size_t)(bm + row) * DM + ch * 8);
            CPA(Ws[0] + so, W + (size_t)(bn + row) * DM + ch * 8);
        }
        CPCOMMIT();
    }

    for (int c = 0; c < 16; c++) {
        int buf = c & 1;
        if (c < 15) {
#pragma unroll
            for (int it = 0; it < 4; it++) {
                int i = tid + it * 256;
                int row = i >> 3, ch = i & 7;
                uint32_t so = SW(row * 128 + ch * 16);
                CPA(As[buf ^ 1] + so,
                    A + (size_t)(bm + row) * DM + (c + 1) * 64 + ch * 8);
                CPA(Ws[buf ^ 1] + so,
                    W + (size_t)(bn + row) * DM + (c + 1) * 64 + ch * 8);
            }
            CPCOMMIT();
            CPWAIT1();
        } else {
            CPWAIT0();
        }
        __syncthreads();

        uint32_t ab = As[buf], wb = Ws[buf];
        int arow = w * 16 + (lane & 15);
        int lch = lane >> 4;
#pragma unroll
        for (int ks = 0; ks < 4; ks++) {
            uint32_t a[4];
            LDSM4(a, ab + SW(arow * 128 + (ks * 2 + lch) * 16));
#pragma unroll
            for (int t8 = 0; t8 < 8; t8++) {
                uint32_t b[4];
                LDSM4(b, wb + SW((t8 * 16 + (lane & 15)) * 128 +
                                 (ks * 2 + lch) * 16));
                mma16816(acc[2 * t8], a, b[0], b[2]);
                mma16816(acc[2 * t8 + 1], a, b[1], b[3]);
            }
        }
        __syncthreads();
    }

    // epilogue
    int m0 = bm + w * 16 + (lane >> 2);
    int c0 = (lane & 3) * 2;
#pragma unroll
    for (int j = 0; j < 16; j++) {
        int n = bn + j * 8 + c0;
        if (mode == 3) {
            float2 x0 = *(const float2*)(xres + (size_t)m0 * DM + n);
            float2 x1 = *(const float2*)(xres + (size_t)(m0 + 8) * DM + n);
            float2 o0 = make_float2(acc[j][0] + x0.x, acc[j][1] + x0.y);
            float2 o1 = make_float2(acc[j][2] + x1.x, acc[j][3] + x1.y);
            *(float2*)(outf + (size_t)m0 * DM + n) = o0;
            *(float2*)(outf + (size_t)(m0 + 8) * DM + n) = o1;
        } else {
            float sc = (mode == 0) ? 0.125f : 1.0f;
            __nv_bfloat16* dstb = (mode == 0) ? g_qb : (mode == 1) ? g_kb : g_vb;
            *(uint32_t*)(dstb + (size_t)m0 * DM + n) =
                pkbf(acc[j][0] * sc, acc[j][1] * sc);
            *(uint32_t*)(dstb + (size_t)(m0 + 8) * DM + n) =
                pkbf(acc[j][2] * sc, acc[j][3] * sc);
        }
    }
}

// ---------------- kernel 4: HMMA flash attention ---------------------------
#define AQ 0
#define AK0 16384
#define AK1 32768
#define AV0 49152
#define AV1 65536
#define ACSQ 81920
#define ACSK 82944
#define ARED 83968
#define ASMEM 84096

__global__ __launch_bounds__(256) void attn_hmma(
    const float* __restrict__ lam_ptr, float* __restrict__ energy)
{
    extern __shared__ char smraw[];
    uint32_t sb = s2u(smraw);
    int tid = threadIdx.x, lane = tid & 31, w = tid >> 5;
    int bh = blockIdx.y;
    int h = bh & (NH - 1);
    int T0 = (bh >> 4) * SEQ;
    int q0 = blockIdx.x * 128;
    float lamh = 0.5f * (*lam_ptr);

    uint32_t Ks[2] = {sb + AK0, sb + AK1};
    uint32_t Vs[2] = {sb + AV0, sb + AV1};
    float2* csq = (float2*)(smraw + ACSQ);
    float2* csk = (float2*)(smraw + ACSK);

    // Q tile -> smem (swizzled), csq
#pragma unroll
    for (int it = 0; it < 4; it++) {
        int i = tid + it * 256;
        int row = i >> 3, ch = i & 7;
        uint4 v = *(const uint4*)(g_qb + (size_t)(T0 + q0 + row) * DM +
                                  h * DH + ch * 8);
        *(uint4*)(smraw + AQ + SW(row * 128 + ch * 16)) = v;
    }
    if (tid < 128) csq[tid] = g_cs2[T0 + q0 + tid];

    // prefetch K/V tile 0
#pragma unroll
    for (int it = 0; it < 4; it++) {
        int i = tid + it * 256;
        int row = i >> 3, ch = i & 7;
        uint32_t so = SW(row * 128 + ch * 16);
        CPA(Ks[0] + so, g_kb + (size_t)(T0 + row) * DM + h * DH + ch * 8);
        CPA(Vs[0] + so, g_vb + (size_t)(T0 + row) * DM + h * DH + ch * 8);
    }
    CPCOMMIT();
    __syncthreads();

    // Q fragments (held in regs all kernel)
    uint32_t qf[4][4];
    {
        int arow = w * 16 + (lane & 15);
        int lch = lane >> 4;
#pragma unroll
        for (int ks = 0; ks < 4; ks++)
            LDSM4(qf[ks], sb + AQ + SW(arow * 128 + (ks * 2 + lch) * 16));
    }

    float oacc[8][4];
#pragma unroll
    for (int j = 0; j < 8; j++)
#pragma unroll
        for (int q = 0; q < 4; q++) oacc[j][q] = 0.f;
    float lp0 = 0.f, lp1 = 0.f;

    int c0 = (lane & 3) * 2;
    float2 qc0 = csq[w * 16 + (lane >> 2)];
    float2 qc1 = csq[w * 16 + (lane >> 2) + 8];

    for (int t = 0; t < 16; t++) {
        int buf = t & 1;
        if (t < 15) {
#pragma unroll
            for (int it = 0; it < 4; it++) {
                int i = tid + it * 256;
                int row = i >> 3, ch = i & 7;
                uint32_t so = SW(row * 128 + ch * 16);
                CPA(Ks[buf ^ 1] + so,
                    g_kb + (size_t)(T0 + (t + 1) * 128 + row) * DM + h * DH + ch * 8);
                CPA(Vs[buf ^ 1] + so,
                    g_vb + (size_t)(T0 + (t + 1) * 128 + row) * DM + h * DH + ch * 8);
            }
            CPCOMMIT();
            CPWAIT1();
        } else {
            CPWAIT0();
        }
        __syncthreads();
        if (tid < 128) csk[tid] = g_cs2[T0 + t * 128 + tid];
        __syncthreads();

        // --- S = Q K^T (per warp: 16 q-rows x 128 cols) ---
        float sacc[16][4];
#pragma unroll
        for (int j = 0; j < 16; j++)
#pragma unroll
            for (int q = 0; q < 4; q++) sacc[j][q] = 0.f;
        int lch = lane >> 4;
#pragma unroll
        for (int ks = 0; ks < 4; ks++) {
#pragma unroll
            for (int t8 = 0; t8 < 8; t8++) {
                uint32_t b[4];
                LDSM4(b, Ks[buf] + SW((t8 * 16 + (lane & 15)) * 128 +
                                      (ks * 2 + lch) * 16));
                mma16816(sacc[2 * t8], qf[ks], b[0], b[2]);
                mma16816(sacc[2 * t8 + 1], qf[ks], b[1], b[3]);
            }
        }

        // --- resonance + exp + PV (A-frags straight from S accumulators) ---
#pragma unroll
        for (int js = 0; js < 8; js++) {
            uint32_t pa[4];
#pragma unroll
            for (int half = 0; half < 2; half++) {
                int j = 2 * js + half;
                float2 kc0 = csk[j * 8 + c0];
                float2 kc1 = csk[j * 8 + c0 + 1];
                float s0 = sacc[j][0] + lamh + lamh * (qc0.x * kc0.x + qc0.y * kc0.y);
                float s1 = sacc[j][1] + lamh + lamh * (qc0.x * kc1.x + qc0.y * kc1.y);
                float s2 = sacc[j][2] + lamh + lamh * (qc1.x * kc0.x + qc1.y * kc0.y);
                float s3 = sacc[j][3] + lamh + lamh * (qc1.x * kc1.x + qc1.y * kc1.y);
                float p0 = __expf(s0), p1 = __expf(s1);
                float p2 = __expf(s2), p3 = __expf(s3);
                lp0 += p0 + p1;
                lp1 += p2 + p3;
                pa[half * 2]     = pkbf(p0, p1);
                pa[half * 2 + 1] = pkbf(p2, p3);
            }
            // wait: a-frag order is {a0,a1,a2,a3} = {(r,k0),(r+8,k0),(r,k8),(r+8,k8)}
            // half0 -> a0,a1 ; half1 -> a2,a3. pa[0]=a0 (p0,p1 row r), pa[1]=a1 (p2,p3 row r+8)
#pragma unroll
            for (int jt = 0; jt < 4; jt++) {
                uint32_t b[4];
                LDSM4T(b, Vs[buf] + SW((js * 16 + (lane & 15)) * 128 +
                                       (2 * jt + lch) * 16));
                mma16816(oacc[2 * jt], pa, b[0], b[1]);
                mma16816(oacc[2 * jt + 1], pa, b[2], b[3]);
            }
        }
        __syncthreads();
    }

    // row sums across the quad (lanes sharing a row)
    lp0 += __shfl_xor_sync(0xffffffffu, lp0, 1);
    lp0 += __shfl_xor_sync(0xffffffffu, lp0, 2);
    lp1 += __shfl_xor_sync(0xffffffffu, lp1, 1);
    lp1 += __shfl_xor_sync(0xffffffffu, lp1, 2);

    int r0g = T0 + q0 + w * 16 + (lane >> 2);
    int r1g = r0g + 8;
    float inv0 = g_headT[r0g * NH + h] / lp0;
    float inv1 = g_headT[r1g * NH + h] / lp1;
    float es = 0.f;
#pragma unroll
    for (int jt = 0; jt < 8; jt++) {
        int d = h * DH + jt * 8 + c0;
        float o0 = oacc[jt][0] * inv0, o1 = oacc[jt][1] * inv0;
        float o2 = oacc[jt][2] * inv1, o3 = oacc[jt][3] * inv1;
        es += fabsf(o0) + fabsf(o1) + fabsf(o2) + fabsf(o3);
        *(uint32_t*)(g_ogb + (size_t)r0g * DM + d) = pkbf(o0, o1);
        *(uint32_t*)(g_ogb + (size_t)r1g * DM + d) = pkbf(o2, o3);
    }
#pragma unroll
    for (int o = 16; o; o >>= 1) es += __shfl_xor_sync(0xffffffffu, es, o);
    float* red = (float*)(smraw + ARED);
    if (lane == 0) red[w] = es;
    __syncthreads();
    if (tid == 0) {
        float tsum = 0.f;
#pragma unroll
        for (int i = 0; i < 8; i++) tsum += red[i];
        atomicAdd(energy, tsum);
    }
}

// ---------------- launch ---------------------------------------------------
extern "C" void kernel_launch(void* const* d_in, const int* in_sizes, int n_in,
                              void* d_out, int out_size)
{
    const float* x       = (const float*)d_in[0];
    const float* Wq      = (const float*)d_in[1];
    const float* Wk      = (const float*)d_in[2];
    const float* Wv      = (const float*)d_in[3];
    const float* Wo      = (const float*)d_in[4];
    const float* Wp      = (const float*)d_in[5];
    const float* gamma   = (const float*)d_in[6];
    const float* beta    = (const float*)d_in[7];
    const float* carrier = (const float*)d_in[8];
    const float* lam     = (const float*)d_in[9];

    float* out    = (float*)d_out;
    float* energy = out + (out_size - 1);

    cudaFuncSetAttribute(gemm_hmma, cudaFuncAttributeMaxDynamicSharedMemorySize, 65536);
    cudaFuncSetAttribute(attn_hmma, cudaFuncAttributeMaxDynamicSharedMemorySize, ASMEM);

    ln_phase_kernel<<<TOK, 256>>>(x, gamma, beta, Wp, carrier, energy);
    wconv_kernel<<<4096, 256>>>(Wq, Wk, Wv, Wo);
    gemm_hmma<<<dim3(8, 32, 3), 256, 65536>>>(nullptr, nullptr, -1);
    attn_hmma<<<dim3(SEQ / 128, 2 * NH), 256, ASMEM>>>(lam, energy);
    gemm_hmma<<<dim3(8, 32, 1), 256, 65536>>>(x, out, 3);
}

// round 5
// speedup vs baseline: 11.5752x; 1.1315x over previous
#include <cuda_runtime.h>
#include <cuda_bf16.h>
#include <math.h>
#include <stdint.h>

#define TOK 4096
#define DM 1024
#define NH 16
#define DH 64
#define SEQ 2048

// ---------------- scratch (device globals) ---------------------------------
__device__ __nv_bfloat16 g_xnb[TOK * DM];
__device__ __nv_bfloat16 g_qb[TOK * DM];
__device__ __nv_bfloat16 g_kb[TOK * DM];
__device__ __nv_bfloat16 g_vb[TOK * DM];
__device__ __nv_bfloat16 g_ogb[TOK * DM];
__device__ __nv_bfloat16 g_wb[4][DM * DM];     // Wq,Wk,Wv,Wo bf16
__device__ float2 g_cs2[TOK];
__device__ float g_headT[TOK * NH];

// ---------------- helpers ---------------------------------------------------
__device__ __forceinline__ uint32_t s2u(const void* p) {
    uint32_t a;
    asm("{ .reg .u64 t; cvta.to.shared.u64 t, %1; cvt.u32.u64 %0, t; }"
        : "=r"(a) : "l"(p));
    return a;
}
__device__ __forceinline__ uint32_t pkbf(float a, float b) {
    __nv_bfloat162 h = __floats2bfloat162_rn(a, b);
    return *reinterpret_cast<uint32_t*>(&h);
}
#define SW(o) ((uint32_t)(o) ^ ((((uint32_t)(o)) >> 3) & 0x70))

#define CPA(dst, src) asm volatile( \
    "cp.async.cg.shared.global [%0], [%1], 16;" :: "r"(dst), "l"(src))
#define CPCOMMIT() asm volatile("cp.async.commit_group;" ::: "memory")
#define CPWAIT1() asm volatile("cp.async.wait_group 1;" ::: "memory")
#define CPWAIT0() asm volatile("cp.async.wait_group 0;" ::: "memory")

#define LDSM4(r, a) asm volatile( \
    "ldmatrix.sync.aligned.m8n8.x4.shared.b16 {%0,%1,%2,%3}, [%4];" \
    : "=r"((r)[0]), "=r"((r)[1]), "=r"((r)[2]), "=r"((r)[3]) : "r"(a))
#define LDSM4T(r, a) asm volatile( \
    "ldmatrix.sync.aligned.m8n8.x4.trans.shared.b16 {%0,%1,%2,%3}, [%4];" \
    : "=r"((r)[0]), "=r"((r)[1]), "=r"((r)[2]), "=r"((r)[3]) : "r"(a))

__device__ __forceinline__ void mma16816(float* d, const uint32_t* a,
                                         uint32_t b0, uint32_t b1) {
    asm volatile(
        "mma.sync.aligned.m16n8k16.row.col.f32.bf16.bf16.f32 "
        "{%0,%1,%2,%3}, {%4,%5,%6,%7}, {%8,%9}, {%0,%1,%2,%3};"
        : "+f"(d[0]), "+f"(d[1]), "+f"(d[2]), "+f"(d[3])
        : "r"(a[0]), "r"(a[1]), "r"(a[2]), "r"(a[3]), "r"(b0), "r"(b1));
}

// ---------------- kernel 1: LayerNorm + phase + gates ----------------------
__global__ __launch_bounds__(256) void ln_phase_kernel(
    const float* __restrict__ x, const float* __restrict__ gamma,
    const float* __restrict__ beta, const float* __restrict__ Wp,
    const float* __restrict__ carrier, float* __restrict__ energy_slot)
{
    int row = blockIdx.x;
    int tid = threadIdx.x;
    __shared__ float red[16];
    __shared__ float bc[2];

    float4 v = ((const float4*)(x + (size_t)row * DM))[tid];
    float s  = v.x + v.y + v.z + v.w;
    float ss = v.x * v.x + v.y * v.y + v.z * v.z + v.w * v.w;
#pragma unroll
    for (int o = 16; o; o >>= 1) {
        s  += __shfl_xor_sync(0xffffffffu, s, o);
        ss += __shfl_xor_sync(0xffffffffu, ss, o);
    }
    int warp = tid >> 5, lane = tid & 31;
    if (lane == 0) { red[warp] = s; red[warp + 8] = ss; }
    __syncthreads();
    if (tid == 0) {
        float a = 0.f, b = 0.f;
#pragma unroll
        for (int i = 0; i < 8; i++) { a += red[i]; b += red[i + 8]; }
        float mu  = a * (1.0f / DM);
        float var = b * (1.0f / DM) - mu * mu;
        bc[0] = mu; bc[1] = rsqrtf(var + 1e-5f);
    }
    __syncthreads();
    float mu = bc[0], rstd = bc[1];

    float4 g  = ((const float4*)gamma)[tid];
    float4 be = ((const float4*)beta)[tid];
    float4 xv;
    xv.x = (v.x - mu) * rstd * g.x + be.x;
    xv.y = (v.y - mu) * rstd * g.y + be.y;
    xv.z = (v.z - mu) * rstd * g.z + be.z;
    xv.w = (v.w - mu) * rstd * g.w + be.w;
    uint32_t* dst = (uint32_t*)(g_xnb + (size_t)row * DM + tid * 4);
    dst[0] = pkbf(xv.x, xv.y);
    dst[1] = pkbf(xv.z, xv.w);

    float4 w = ((const float4*)Wp)[tid];
    float p = xv.x * w.x + xv.y * w.y + xv.z * w.z + xv.w * w.w;
#pragma unroll
    for (int o = 16; o; o >>= 1) p += __shfl_xor_sync(0xffffffffu, p, o);
    __syncthreads();
    if (lane == 0) red[warp] = p;
    __syncthreads();
    if (tid == 0) {
        float a = 0.f;
#pragma unroll
        for (int i = 0; i < 8; i++) a += red[i];
        bc[0] = a;
    }
    __syncthreads();
    float phase = bc[0];
    if (tid == 0) g_cs2[row] = make_float2(cosf(phase), sinf(phase));
    if (tid < NH) {
        float c = cosf((phase - carrier[tid]) * 0.5f);
        g_headT[row * NH + tid] = c * c;
    }
    if (row == 0 && tid == 0) *energy_slot = 0.f;
}

// ---------------- kernel 2: weight fp32->bf16 ------------------------------
__global__ __launch_bounds__(256) void wconv_kernel(
    const float* __restrict__ W0, const float* __restrict__ W1,
    const float* __restrict__ W2, const float* __restrict__ W3)
{
    int gid = blockIdx.x * 256 + threadIdx.x;
    int a = gid >> 18, r = gid & 0x3FFFF;
    const float* src = (a == 0) ? W0 : (a == 1) ? W1 : (a == 2) ? W2 : W3;
    float4 v = ((const float4*)src)[r];
    uint32_t* d = (uint32_t*)(&g_wb[a][0] + (size_t)r * 4);
    d[0] = pkbf(v.x, v.y);
    d[1] = pkbf(v.z, v.w);
}

// ---------------- kernel 3: HMMA GEMM  C = A @ W^T -------------------------
// mode 0: Q (scale 0.125)  1: K  2: V  3: out fp32 + residual
__global__ __launch_bounds__(256, 2) void gemm_hmma(
    const float* __restrict__ xres, float* __restrict__ outf, int modeParam)
{
    extern __shared__ char smraw[];
    uint32_t sb = s2u(smraw);
    int tid = threadIdx.x, lane = tid & 31, w = tid >> 5;
    int mode = (modeParam >= 0) ? modeParam : blockIdx.z;
    const __nv_bfloat16* A = (mode == 3) ? g_ogb : g_xnb;
    const __nv_bfloat16* W = g_wb[mode];
    int bm = blockIdx.y * 128, bn = blockIdx.x * 128;
    uint32_t As[2] = {sb, sb + 16384};
    uint32_t Ws[2] = {sb + 32768, sb + 49152};

    float acc[16][4];
#pragma unroll
    for (int j = 0; j < 16; j++)
#pragma unroll
        for (int q = 0; q < 4; q++) acc[j][q] = 0.f;

    // prologue load chunk 0
    {
#pragma unroll
        for (int it = 0; it < 4; it++) {
            int i = tid + it * 256;
            int row = i >> 3, ch = i & 7;
            uint32_t so = SW(row * 128 + ch * 16);
            CPA(As[0] + so, A + (size_t)(bm + row) * DM + ch * 8);
            CPA(Ws[0] + so, W + (size_t)(bn + row) * DM + ch * 8);
        }
        CPCOMMIT();
    }

    for (int c = 0; c < 16; c++) {
        int buf = c & 1;
        if (c < 15) {
#pragma unroll
            for (int it = 0; it < 4; it++) {
                int i = tid + it * 256;
                int row = i >> 3, ch = i & 7;
                uint32_t so = SW(row * 128 + ch * 16);
                CPA(As[buf ^ 1] + so,
                    A + (size_t)(bm + row) * DM + (c + 1) * 64 + ch * 8);
                CPA(Ws[buf ^ 1] + so,
                    W + (size_t)(bn + row) * DM + (c + 1) * 64 + ch * 8);
            }
            CPCOMMIT();
            CPWAIT1();
        } else {
            CPWAIT0();
        }
        __syncthreads();

        uint32_t ab = As[buf], wb = Ws[buf];
        int arow = w * 16 + (lane & 15);
        int lch = lane >> 4;
#pragma unroll
        for (int ks = 0; ks < 4; ks++) {
            uint32_t a[4];
            LDSM4(a, ab + SW(arow * 128 + (ks * 2 + lch) * 16));
#pragma unroll
            for (int t8 = 0; t8 < 8; t8++) {
                uint32_t b[4];
                LDSM4(b, wb + SW((t8 * 16 + (lane & 15)) * 128 +
                                 (ks * 2 + lch) * 16));
                mma16816(acc[2 * t8], a, b[0], b[2]);
                mma16816(acc[2 * t8 + 1], a, b[1], b[3]);
            }
        }
        __syncthreads();
    }

    // epilogue
    int m0 = bm + w * 16 + (lane >> 2);
    int c0 = (lane & 3) * 2;
#pragma unroll
    for (int j = 0; j < 16; j++) {
        int n = bn + j * 8 + c0;
        if (mode == 3) {
            float2 x0 = *(const float2*)(xres + (size_t)m0 * DM + n);
            float2 x1 = *(const float2*)(xres + (size_t)(m0 + 8) * DM + n);
            float2 o0 = make_float2(acc[j][0] + x0.x, acc[j][1] + x0.y);
            float2 o1 = make_float2(acc[j][2] + x1.x, acc[j][3] + x1.y);
            *(float2*)(outf + (size_t)m0 * DM + n) = o0;
            *(float2*)(outf + (size_t)(m0 + 8) * DM + n) = o1;
        } else {
            float sc = (mode == 0) ? 0.125f : 1.0f;
            __nv_bfloat16* dstb = (mode == 0) ? g_qb : (mode == 1) ? g_kb : g_vb;
            *(uint32_t*)(dstb + (size_t)m0 * DM + n) =
                pkbf(acc[j][0] * sc, acc[j][1] * sc);
            *(uint32_t*)(dstb + (size_t)(m0 + 8) * DM + n) =
                pkbf(acc[j][2] * sc, acc[j][3] * sc);
        }
    }
}

// ---------------- kernel 4: HMMA flash attention ---------------------------
#define AQ 0
#define AK0 16384
#define AK1 32768
#define AV0 49152
#define AV1 65536
#define ACSQ 81920
#define ACSK 82944
#define ARED 83968
#define ASMEM 84096

__global__ __launch_bounds__(256, 2) void attn_hmma(
    const float* __restrict__ lam_ptr, float* __restrict__ energy)
{
    extern __shared__ char smraw[];
    uint32_t sb = s2u(smraw);
    int tid = threadIdx.x, lane = tid & 31, w = tid >> 5;
    int bh = blockIdx.y;
    int h = bh & (NH - 1);
    int T0 = (bh >> 4) * SEQ;
    int q0 = blockIdx.x * 128;
    float lamh = 0.5f * (*lam_ptr);

    uint32_t Ks[2] = {sb + AK0, sb + AK1};
    uint32_t Vs[2] = {sb + AV0, sb + AV1};
    float2* csq = (float2*)(smraw + ACSQ);
    float2* csk = (float2*)(smraw + ACSK);

    // Q tile -> smem (swizzled), csq
#pragma unroll
    for (int it = 0; it < 4; it++) {
        int i = tid + it * 256;
        int row = i >> 3, ch = i & 7;
        uint4 v = *(const uint4*)(g_qb + (size_t)(T0 + q0 + row) * DM +
                                  h * DH + ch * 8);
        *(uint4*)(smraw + AQ + SW(row * 128 + ch * 16)) = v;
    }
    if (tid < 128) csq[tid] = g_cs2[T0 + q0 + tid];

    // prefetch K/V tile 0
#pragma unroll
    for (int it = 0; it < 4; it++) {
        int i = tid + it * 256;
        int row = i >> 3, ch = i & 7;
        uint32_t so = SW(row * 128 + ch * 16);
        CPA(Ks[0] + so, g_kb + (size_t)(T0 + row) * DM + h * DH + ch * 8);
        CPA(Vs[0] + so, g_vb + (size_t)(T0 + row) * DM + h * DH + ch * 8);
    }
    CPCOMMIT();
    __syncthreads();

    // Q fragments (held in regs all kernel)
    uint32_t qf[4][4];
    {
        int arow = w * 16 + (lane & 15);
        int lch = lane >> 4;
#pragma unroll
        for (int ks = 0; ks < 4; ks++)
            LDSM4(qf[ks], sb + AQ + SW(arow * 128 + (ks * 2 + lch) * 16));
    }

    float oacc[8][4];
#pragma unroll
    for (int j = 0; j < 8; j++)
#pragma unroll
        for (int q = 0; q < 4; q++) oacc[j][q] = 0.f;
    float lp0 = 0.f, lp1 = 0.f;

    int c0 = (lane & 3) * 2;
    float2 qc0 = csq[w * 16 + (lane >> 2)];
    float2 qc1 = csq[w * 16 + (lane >> 2) + 8];

    for (int t = 0; t < 16; t++) {
        int buf = t & 1;
        if (t < 15) {
#pragma unroll
            for (int it = 0; it < 4; it++) {
                int i = tid + it * 256;
                int row = i >> 3, ch = i & 7;
                uint32_t so = SW(row * 128 + ch * 16);
                CPA(Ks[buf ^ 1] + so,
                    g_kb + (size_t)(T0 + (t + 1) * 128 + row) * DM + h * DH + ch * 8);
                CPA(Vs[buf ^ 1] + so,
                    g_vb + (size_t)(T0 + (t + 1) * 128 + row) * DM + h * DH + ch * 8);
            }
            CPCOMMIT();
            CPWAIT1();
        } else {
            CPWAIT0();
        }
        __syncthreads();
        if (tid < 128) csk[tid] = g_cs2[T0 + t * 128 + tid];
        __syncthreads();

        int lch = lane >> 4;
        // --- per 16-key block: S (8 HMMA) -> exp -> PV (8 HMMA) ---
        // keeps live sacc at 8 regs and interleaves MUFU with tensor ops
#pragma unroll
        for (int t8 = 0; t8 < 8; t8++) {
            float sacc[2][4];
#pragma unroll
            for (int q = 0; q < 4; q++) { sacc[0][q] = 0.f; sacc[1][q] = 0.f; }
#pragma unroll
            for (int ks = 0; ks < 4; ks++) {
                uint32_t b[4];
                LDSM4(b, Ks[buf] + SW((t8 * 16 + (lane & 15)) * 128 +
                                      (ks * 2 + lch) * 16));
                mma16816(sacc[0], qf[ks], b[0], b[2]);
                mma16816(sacc[1], qf[ks], b[1], b[3]);
            }

            uint32_t pa[4];
#pragma unroll
            for (int half = 0; half < 2; half++) {
                float2 kc0 = csk[t8 * 16 + half * 8 + c0];
                float2 kc1 = csk[t8 * 16 + half * 8 + c0 + 1];
                float s0 = sacc[half][0] + lamh + lamh * (qc0.x * kc0.x + qc0.y * kc0.y);
                float s1 = sacc[half][1] + lamh + lamh * (qc0.x * kc1.x + qc0.y * kc1.y);
                float s2 = sacc[half][2] + lamh + lamh * (qc1.x * kc0.x + qc1.y * kc0.y);
                float s3 = sacc[half][3] + lamh + lamh * (qc1.x * kc1.x + qc1.y * kc1.y);
                float p0 = __expf(s0), p1 = __expf(s1);
                float p2 = __expf(s2), p3 = __expf(s3);
                lp0 += p0 + p1;
                lp1 += p2 + p3;
                pa[half * 2]     = pkbf(p0, p1);
                pa[half * 2 + 1] = pkbf(p2, p3);
            }
#pragma unroll
            for (int jt = 0; jt < 4; jt++) {
                uint32_t b[4];
                LDSM4T(b, Vs[buf] + SW((t8 * 16 + (lane & 15)) * 128 +
                                       (2 * jt + lch) * 16));
                mma16816(oacc[2 * jt], pa, b[0], b[1]);
                mma16816(oacc[2 * jt + 1], pa, b[2], b[3]);
            }
        }
        __syncthreads();
    }

    // row sums across the quad (lanes sharing a row)
    lp0 += __shfl_xor_sync(0xffffffffu, lp0, 1);
    lp0 += __shfl_xor_sync(0xffffffffu, lp0, 2);
    lp1 += __shfl_xor_sync(0xffffffffu, lp1, 1);
    lp1 += __shfl_xor_sync(0xffffffffu, lp1, 2);

    int r0g = T0 + q0 + w * 16 + (lane >> 2);
    int r1g = r0g + 8;
    float inv0 = g_headT[r0g * NH + h] / lp0;
    float inv1 = g_headT[r1g * NH + h] / lp1;
    float es = 0.f;
#pragma unroll
    for (int jt = 0; jt < 8; jt++) {
        int d = h * DH + jt * 8 + c0;
        float o0 = oacc[jt][0] * inv0, o1 = oacc[jt][1] * inv0;
        float o2 = oacc[jt][2] * inv1, o3 = oacc[jt][3] * inv1;
        es += fabsf(o0) + fabsf(o1) + fabsf(o2) + fabsf(o3);
        *(uint32_t*)(g_ogb + (size_t)r0g * DM + d) = pkbf(o0, o1);
        *(uint32_t*)(g_ogb + (size_t)r1g * DM + d) = pkbf(o2, o3);
    }
#pragma unroll
    for (int o = 16; o; o >>= 1) es += __shfl_xor_sync(0xffffffffu, es, o);
    float* red = (float*)(smraw + ARED);
    if (lane == 0) red[w] = es;
    __syncthreads();
    if (tid == 0) {
        float tsum = 0.f;
#pragma unroll
        for (int i = 0; i < 8; i++) tsum += red[i];
        atomicAdd(energy, tsum);
    }
}

// ---------------- launch ---------------------------------------------------
extern "C" void kernel_launch(void* const* d_in, const int* in_sizes, int n_in,
                              void* d_out, int out_size)
{
    const float* x       = (const float*)d_in[0];
    const float* Wq      = (const float*)d_in[1];
    const float* Wk      = (const float*)d_in[2];
    const float* Wv      = (const float*)d_in[3];
    const float* Wo      = (const float*)d_in[4];
    const float* Wp      = (const float*)d_in[5];
    const float* gamma   = (const float*)d_in[6];
    const float* beta    = (const float*)d_in[7];
    const float* carrier = (const float*)d_in[8];
    const float* lam     = (const float*)d_in[9];

    float* out    = (float*)d_out;
    float* energy = out + (out_size - 1);

    cudaFuncSetAttribute(gemm_hmma, cudaFuncAttributeMaxDynamicSharedMemorySize, 65536);
    cudaFuncSetAttribute(attn_hmma, cudaFuncAttributeMaxDynamicSharedMemorySize, ASMEM);

    ln_phase_kernel<<<TOK, 256>>>(x, gamma, beta, Wp, carrier, energy);
    wconv_kernel<<<4096, 256>>>(Wq, Wk, Wv, Wo);
    gemm_hmma<<<dim3(8, 32, 3), 256, 65536>>>(nullptr, nullptr, -1);
    attn_hmma<<<dim3(SEQ / 128, 2 * NH), 256, ASMEM>>>(lam, energy);
    gemm_hmma<<<dim3(8, 32, 1), 256, 65536>>>(x, out, 3);
}

// round 6
// speedup vs baseline: 12.3448x; 1.0665x over previous
#include <cuda_runtime.h>
#include <cuda_bf16.h>
#include <math.h>
#include <stdint.h>

#define TOK 4096
#define DM 1024
#define NH 16
#define DH 64
#define SEQ 2048

// ---------------- scratch (device globals) ---------------------------------
__device__ __nv_bfloat16 g_xnb[TOK * DM];
__device__ __nv_bfloat16 g_qb[TOK * DM];
__device__ __nv_bfloat16 g_kb[TOK * DM];
__device__ __nv_bfloat16 g_vb[TOK * DM];
__device__ __nv_bfloat16 g_ogb[TOK * DM];
__device__ __nv_bfloat16 g_wb[4][DM * DM];     // Wq,Wk,Wv,Wo bf16
__device__ float2 g_cs2[TOK];
__device__ float g_headT[TOK * NH];

// ---------------- helpers ---------------------------------------------------
__device__ __forceinline__ uint32_t s2u(const void* p) {
    uint32_t a;
    asm("{ .reg .u64 t; cvta.to.shared.u64 t, %1; cvt.u32.u64 %0, t; }"
        : "=r"(a) : "l"(p));
    return a;
}
__device__ __forceinline__ uint32_t pkbf(float a, float b) {
    __nv_bfloat162 h = __floats2bfloat162_rn(a, b);
    return *reinterpret_cast<uint32_t*>(&h);
}
__device__ __forceinline__ float ex2f(float x) {
    float y;
    asm("ex2.approx.ftz.f32 %0, %1;" : "=f"(y) : "f"(x));
    return y;
}
#define SW(o) ((uint32_t)(o) ^ ((((uint32_t)(o)) >> 3) & 0x70))

#define CPA(dst, src) asm volatile( \
    "cp.async.cg.shared.global [%0], [%1], 16;" :: "r"(dst), "l"(src))
#define CPCOMMIT() asm volatile("cp.async.commit_group;" ::: "memory")
#define CPWAIT1() asm volatile("cp.async.wait_group 1;" ::: "memory")
#define CPWAIT0() asm volatile("cp.async.wait_group 0;" ::: "memory")

#define LDSM4(r, a) asm volatile( \
    "ldmatrix.sync.aligned.m8n8.x4.shared.b16 {%0,%1,%2,%3}, [%4];" \
    : "=r"((r)[0]), "=r"((r)[1]), "=r"((r)[2]), "=r"((r)[3]) : "r"(a))
#define LDSM4T(r, a) asm volatile( \
    "ldmatrix.sync.aligned.m8n8.x4.trans.shared.b16 {%0,%1,%2,%3}, [%4];" \
    : "=r"((r)[0]), "=r"((r)[1]), "=r"((r)[2]), "=r"((r)[3]) : "r"(a))

__device__ __forceinline__ void mma16816(float* d, const uint32_t* a,
                                         uint32_t b0, uint32_t b1) {
    asm volatile(
        "mma.sync.aligned.m16n8k16.row.col.f32.bf16.bf16.f32 "
        "{%0,%1,%2,%3}, {%4,%5,%6,%7}, {%8,%9}, {%0,%1,%2,%3};"
        : "+f"(d[0]), "+f"(d[1]), "+f"(d[2]), "+f"(d[3])
        : "r"(a[0]), "r"(a[1]), "r"(a[2]), "r"(a[3]), "r"(b0), "r"(b1));
}

// ---------------- kernel 1: LayerNorm + phase + gates ----------------------
__global__ __launch_bounds__(256) void ln_phase_kernel(
    const float* __restrict__ x, const float* __restrict__ gamma,
    const float* __restrict__ beta, const float* __restrict__ Wp,
    const float* __restrict__ carrier, float* __restrict__ energy_slot)
{
    int row = blockIdx.x;
    int tid = threadIdx.x;
    __shared__ float red[16];
    __shared__ float bc[2];

    float4 v = ((const float4*)(x + (size_t)row * DM))[tid];
    float s  = v.x + v.y + v.z + v.w;
    float ss = v.x * v.x + v.y * v.y + v.z * v.z + v.w * v.w;
#pragma unroll
    for (int o = 16; o; o >>= 1) {
        s  += __shfl_xor_sync(0xffffffffu, s, o);
        ss += __shfl_xor_sync(0xffffffffu, ss, o);
    }
    int warp = tid >> 5, lane = tid & 31;
    if (lane == 0) { red[warp] = s; red[warp + 8] = ss; }
    __syncthreads();
    if (tid == 0) {
        float a = 0.f, b = 0.f;
#pragma unroll
        for (int i = 0; i < 8; i++) { a += red[i]; b += red[i + 8]; }
        float mu  = a * (1.0f / DM);
        float var = b * (1.0f / DM) - mu * mu;
        bc[0] = mu; bc[1] = rsqrtf(var + 1e-5f);
    }
    __syncthreads();
    float mu = bc[0], rstd = bc[1];

    float4 g  = ((const float4*)gamma)[tid];
    float4 be = ((const float4*)beta)[tid];
    float4 xv;
    xv.x = (v.x - mu) * rstd * g.x + be.x;
    xv.y = (v.y - mu) * rstd * g.y + be.y;
    xv.z = (v.z - mu) * rstd * g.z + be.z;
    xv.w = (v.w - mu) * rstd * g.w + be.w;
    uint32_t* dst = (uint32_t*)(g_xnb + (size_t)row * DM + tid * 4);
    dst[0] = pkbf(xv.x, xv.y);
    dst[1] = pkbf(xv.z, xv.w);

    float4 w = ((const float4*)Wp)[tid];
    float p = xv.x * w.x + xv.y * w.y + xv.z * w.z + xv.w * w.w;
#pragma unroll
    for (int o = 16; o; o >>= 1) p += __shfl_xor_sync(0xffffffffu, p, o);
    __syncthreads();
    if (lane == 0) red[warp] = p;
    __syncthreads();
    if (tid == 0) {
        float a = 0.f;
#pragma unroll
        for (int i = 0; i < 8; i++) a += red[i];
        bc[0] = a;
    }
    __syncthreads();
    float phase = bc[0];
    if (tid == 0) g_cs2[row] = make_float2(cosf(phase), sinf(phase));
    if (tid < NH) {
        float c = cosf((phase - carrier[tid]) * 0.5f);
        g_headT[row * NH + tid] = c * c;
    }
    if (row == 0 && tid == 0) *energy_slot = 0.f;
}

// ---------------- kernel 2: weight fp32->bf16 ------------------------------
__global__ __launch_bounds__(256) void wconv_kernel(
    const float* __restrict__ W0, const float* __restrict__ W1,
    const float* __restrict__ W2, const float* __restrict__ W3)
{
    int gid = blockIdx.x * 256 + threadIdx.x;
    int a = gid >> 18, r = gid & 0x3FFFF;
    const float* src = (a == 0) ? W0 : (a == 1) ? W1 : (a == 2) ? W2 : W3;
    float4 v = ((const float4*)src)[r];
    uint32_t* d = (uint32_t*)(&g_wb[a][0] + (size_t)r * 4);
    d[0] = pkbf(v.x, v.y);
    d[1] = pkbf(v.z, v.w);
}

// ---------------- kernel 3: HMMA GEMM  C = A @ W^T -------------------------
// mode 0: Q (scale 0.125*log2e)  1: K  2: V  3: out fp32 + residual
__global__ __launch_bounds__(256, 2) void gemm_hmma(
    const float* __restrict__ xres, float* __restrict__ outf, int modeParam)
{
    extern __shared__ char smraw[];
    uint32_t sb = s2u(smraw);
    int tid = threadIdx.x, lane = tid & 31, w = tid >> 5;
    int mode = (modeParam >= 0) ? modeParam : blockIdx.z;
    const __nv_bfloat16* A = (mode == 3) ? g_ogb : g_xnb;
    const __nv_bfloat16* W = g_wb[mode];
    int bm = blockIdx.y * 128, bn = blockIdx.x * 128;
    uint32_t As[2] = {sb, sb + 16384};
    uint32_t Ws[2] = {sb + 32768, sb + 49152};

    float acc[16][4];
#pragma unroll
    for (int j = 0; j < 16; j++)
#pragma unroll
        for (int q = 0; q < 4; q++) acc[j][q] = 0.f;

    // prologue load chunk 0
    {
#pragma unroll
        for (int it = 0; it < 4; it++) {
            int i = tid + it * 256;
            int row = i >> 3, ch = i & 7;
            uint32_t so = SW(row * 128 + ch * 16);
            CPA(As[0] + so, A + (size_t)(bm + row) * DM + ch * 8);
            CPA(Ws[0] + so, W + (size_t)(bn + row) * DM + ch * 8);
        }
        CPCOMMIT();
    }

    for (int c = 0; c < 16; c++) {
        int buf = c & 1;
        if (c < 15) {
#pragma unroll
            for (int it = 0; it < 4; it++) {
                int i = tid + it * 256;
                int row = i >> 3, ch = i & 7;
                uint32_t so = SW(row * 128 + ch * 16);
                CPA(As[buf ^ 1] + so,
                    A + (size_t)(bm + row) * DM + (c + 1) * 64 + ch * 8);
                CPA(Ws[buf ^ 1] + so,
                    W + (size_t)(bn + row) * DM + (c + 1) * 64 + ch * 8);
            }
            CPCOMMIT();
            CPWAIT1();
        } else {
            CPWAIT0();
        }
        __syncthreads();

        uint32_t ab = As[buf], wb = Ws[buf];
        int arow = w * 16 + (lane & 15);
        int lch = lane >> 4;
#pragma unroll
        for (int ks = 0; ks < 4; ks++) {
            uint32_t a[4];
            LDSM4(a, ab + SW(arow * 128 + (ks * 2 + lch) * 16));
#pragma unroll
            for (int t8 = 0; t8 < 8; t8++) {
                uint32_t b[4];
                LDSM4(b, wb + SW((t8 * 16 + (lane & 15)) * 128 +
                                 (ks * 2 + lch) * 16));
                mma16816(acc[2 * t8], a, b[0], b[2]);
                mma16816(acc[2 * t8 + 1], a, b[1], b[3]);
            }
        }
        __syncthreads();
    }

    // epilogue
    int m0 = bm + w * 16 + (lane >> 2);
    int c0 = (lane & 3) * 2;
#pragma unroll
    for (int j = 0; j < 16; j++) {
        int n = bn + j * 8 + c0;
        if (mode == 3) {
            float2 x0 = *(const float2*)(xres + (size_t)m0 * DM + n);
            float2 x1 = *(const float2*)(xres + (size_t)(m0 + 8) * DM + n);
            float2 o0 = make_float2(acc[j][0] + x0.x, acc[j][1] + x0.y);
            float2 o1 = make_float2(acc[j][2] + x1.x, acc[j][3] + x1.y);
            *(float2*)(outf + (size_t)m0 * DM + n) = o0;
            *(float2*)(outf + (size_t)(m0 + 8) * DM + n) = o1;
        } else {
            // Q pre-scaled by (1/8)*log2e so softmax uses raw EX2
            float sc = (mode == 0) ? 0.125f * 1.44269504f : 1.0f;
            __nv_bfloat16* dstb = (mode == 0) ? g_qb : (mode == 1) ? g_kb : g_vb;
            *(uint32_t*)(dstb + (size_t)m0 * DM + n) =
                pkbf(acc[j][0] * sc, acc[j][1] * sc);
            *(uint32_t*)(dstb + (size_t)(m0 + 8) * DM + n) =
                pkbf(acc[j][2] * sc, acc[j][3] * sc);
        }
    }
}

// ---------------- kernel 4: HMMA flash attention ---------------------------
// resonance folded into QK via a 5th k=16 MMA step:
//   A-ext row i: [lamh*log2e*cos_i, lamh*log2e*sin_i, lamh*log2e, 0...]
//   B-ext row j: [cos_j, sin_j, 1, 0...]
#define AQ 0
#define ACQ 16384
#define AK0 20480
#define AK1 36864
#define AV0 53248
#define AV1 69632
#define ACK0 86016
#define ACK1 90112
#define ARED 94208
#define ASMEM 94336

__global__ __launch_bounds__(256, 2) void attn_hmma(
    const float* __restrict__ lam_ptr, float* __restrict__ energy)
{
    extern __shared__ char smraw[];
    uint32_t sb = s2u(smraw);
    int tid = threadIdx.x, lane = tid & 31, w = tid >> 5;
    int bh = blockIdx.y;
    int h = bh & (NH - 1);
    int T0 = (bh >> 4) * SEQ;
    int q0 = blockIdx.x * 128;
    float laml2 = 0.5f * (*lam_ptr) * 1.44269504f;

    uint32_t Ks[2]  = {sb + AK0, sb + AK1};
    uint32_t Vs[2]  = {sb + AV0, sb + AV1};
    uint32_t CKs[2] = {sb + ACK0, sb + ACK1};

    // Q tile -> smem (swizzled); CQ ext tile (128 rows x 32B)
#pragma unroll
    for (int it = 0; it < 4; it++) {
        int i = tid + it * 256;
        int row = i >> 3, ch = i & 7;
        uint4 v = *(const uint4*)(g_qb + (size_t)(T0 + q0 + row) * DM +
                                  h * DH + ch * 8);
        *(uint4*)(smraw + AQ + SW(row * 128 + ch * 16)) = v;
    }
    if (tid < 128) {
        float2 cs = g_cs2[T0 + q0 + tid];
        uint32_t* d = (uint32_t*)(smraw + ACQ + tid * 32);
        d[0] = pkbf(laml2 * cs.x, laml2 * cs.y);
        d[1] = pkbf(laml2, 0.f);
        d[2] = 0; d[3] = 0; d[4] = 0; d[5] = 0; d[6] = 0; d[7] = 0;
    }

    // prefetch K/V tile 0 + build CK0
#pragma unroll
    for (int it = 0; it < 4; it++) {
        int i = tid + it * 256;
        int row = i >> 3, ch = i & 7;
        uint32_t so = SW(row * 128 + ch * 16);
        CPA(Ks[0] + so, g_kb + (size_t)(T0 + row) * DM + h * DH + ch * 8);
        CPA(Vs[0] + so, g_vb + (size_t)(T0 + row) * DM + h * DH + ch * 8);
    }
    CPCOMMIT();
    if (tid < 128) {
        float2 cs = g_cs2[T0 + tid];
        uint32_t* d = (uint32_t*)(smraw + ACK0 + tid * 32);
        d[0] = pkbf(cs.x, cs.y);
        d[1] = pkbf(1.f, 0.f);
        d[2] = 0; d[3] = 0; d[4] = 0; d[5] = 0; d[6] = 0; d[7] = 0;
    }
    __syncthreads();

    // Q + CQ fragments (held in regs all kernel): 5 k-steps
    uint32_t qf[5][4];
    {
        int arow = w * 16 + (lane & 15);
        int lch = lane >> 4;
#pragma unroll
        for (int ks = 0; ks < 4; ks++)
            LDSM4(qf[ks], sb + AQ + SW(arow * 128 + (ks * 2 + lch) * 16));
        LDSM4(qf[4], sb + ACQ + arow * 32 + lch * 16);
    }

    float oacc[8][4];
#pragma unroll
    for (int j = 0; j < 8; j++)
#pragma unroll
        for (int q = 0; q < 4; q++) oacc[j][q] = 0.f;
    float lp0 = 0.f, lp1 = 0.f;

    for (int t = 0; t < 16; t++) {
        int buf = t & 1;
        if (t < 15) {
#pragma unroll
            for (int it = 0; it < 4; it++) {
                int i = tid + it * 256;
                int row = i >> 3, ch = i & 7;
                uint32_t so = SW(row * 128 + ch * 16);
                CPA(Ks[buf ^ 1] + so,
                    g_kb + (size_t)(T0 + (t + 1) * 128 + row) * DM + h * DH + ch * 8);
                CPA(Vs[buf ^ 1] + so,
                    g_vb + (size_t)(T0 + (t + 1) * 128 + row) * DM + h * DH + ch * 8);
            }
            CPCOMMIT();
            if (tid < 128) {
                float2 cs = g_cs2[T0 + (t + 1) * 128 + tid];
                uint32_t* d = (uint32_t*)(smraw + (buf ? ACK0 : ACK1) + tid * 32);
                d[0] = pkbf(cs.x, cs.y);
                d[1] = pkbf(1.f, 0.f);
                d[2] = 0; d[3] = 0; d[4] = 0; d[5] = 0; d[6] = 0; d[7] = 0;
            }
            CPWAIT1();
        } else {
            CPWAIT0();
        }
        __syncthreads();

        int lch = lane >> 4;
        // --- per 16-key block: S (10 HMMA incl resonance) -> EX2 -> PV (8) ---
#pragma unroll
        for (int t8 = 0; t8 < 8; t8++) {
            float sacc[2][4];
#pragma unroll
            for (int q = 0; q < 4; q++) { sacc[0][q] = 0.f; sacc[1][q] = 0.f; }
#pragma unroll
            for (int ks = 0; ks < 4; ks++) {
                uint32_t b[4];
                LDSM4(b, Ks[buf] + SW((t8 * 16 + (lane & 15)) * 128 +
                                      (ks * 2 + lch) * 16));
                mma16816(sacc[0], qf[ks], b[0], b[2]);
                mma16816(sacc[1], qf[ks], b[1], b[3]);
            }
            {   // resonance k-step
                uint32_t b[4];
                LDSM4(b, CKs[buf] + (t8 * 16 + (lane & 15)) * 32 + lch * 16);
                mma16816(sacc[0], qf[4], b[0], b[2]);
                mma16816(sacc[1], qf[4], b[1], b[3]);
            }

            uint32_t pa[4];
#pragma unroll
            for (int half = 0; half < 2; half++) {
                float p0 = ex2f(sacc[half][0]);
                float p1 = ex2f(sacc[half][1]);
                float p2 = ex2f(sacc[half][2]);
                float p3 = ex2f(sacc[half][3]);
                lp0 += p0 + p1;
                lp1 += p2 + p3;
                pa[half * 2]     = pkbf(p0, p1);
                pa[half * 2 + 1] = pkbf(p2, p3);
            }
#pragma unroll
            for (int jt = 0; jt < 4; jt++) {
                uint32_t b[4];
                LDSM4T(b, Vs[buf] + SW((t8 * 16 + (lane & 15)) * 128 +
                                       (2 * jt + lch) * 16));
                mma16816(oacc[2 * jt], pa, b[0], b[1]);
                mma16816(oacc[2 * jt + 1], pa, b[2], b[3]);
            }
        }
        __syncthreads();
    }

    // row sums across the quad (lanes sharing a row)
    lp0 += __shfl_xor_sync(0xffffffffu, lp0, 1);
    lp0 += __shfl_xor_sync(0xffffffffu, lp0, 2);
    lp1 += __shfl_xor_sync(0xffffffffu, lp1, 1);
    lp1 += __shfl_xor_sync(0xffffffffu, lp1, 2);

    int c0 = (lane & 3) * 2;
    int r0g = T0 + q0 + w * 16 + (lane >> 2);
    int r1g = r0g + 8;
    float inv0 = g_headT[r0g * NH + h] / lp0;
    float inv1 = g_headT[r1g * NH + h] / lp1;
    float es = 0.f;
#pragma unroll
    for (int jt = 0; jt < 8; jt++) {
        int d = h * DH + jt * 8 + c0;
        float o0 = oacc[jt][0] * inv0, o1 = oacc[jt][1] * inv0;
        float o2 = oacc[jt][2] * inv1, o3 = oacc[jt][3] * inv1;
        es += fabsf(o0) + fabsf(o1) + fabsf(o2) + fabsf(o3);
        *(uint32_t*)(g_ogb + (size_t)r0g * DM + d) = pkbf(o0, o1);
        *(uint32_t*)(g_ogb + (size_t)r1g * DM + d) = pkbf(o2, o3);
    }
#pragma unroll
    for (int o = 16; o; o >>= 1) es += __shfl_xor_sync(0xffffffffu, es, o);
    float* red = (float*)(smraw + ARED);
    if (lane == 0) red[w] = es;
    __syncthreads();
    if (tid == 0) {
        float tsum = 0.f;
#pragma unroll
        for (int i = 0; i < 8; i++) tsum += red[i];
        atomicAdd(energy, tsum);
    }
}

// ---------------- launch ---------------------------------------------------
extern "C" void kernel_launch(void* const* d_in, const int* in_sizes, int n_in,
                              void* d_out, int out_size)
{
    const float* x       = (const float*)d_in[0];
    const float* Wq      = (const float*)d_in[1];
    const float* Wk      = (const float*)d_in[2];
    const float* Wv      = (const float*)d_in[3];
    const float* Wo      = (const float*)d_in[4];
    const float* Wp      = (const float*)d_in[5];
    const float* gamma   = (const float*)d_in[6];
    const float* beta    = (const float*)d_in[7];
    const float* carrier = (const float*)d_in[8];
    const float* lam     = (const float*)d_in[9];

    float* out    = (float*)d_out;
    float* energy = out + (out_size - 1);

    cudaFuncSetAttribute(gemm_hmma, cudaFuncAttributeMaxDynamicSharedMemorySize, 65536);
    cudaFuncSetAttribute(attn_hmma, cudaFuncAttributeMaxDynamicSharedMemorySize, ASMEM);

    ln_phase_kernel<<<TOK, 256>>>(x, gamma, beta, Wp, carrier, energy);
    wconv_kernel<<<4096, 256>>>(Wq, Wk, Wv, Wo);
    gemm_hmma<<<dim3(8, 32, 3), 256, 65536>>>(nullptr, nullptr, -1);
    attn_hmma<<<dim3(SEQ / 128, 2 * NH), 256, ASMEM>>>(lam, energy);
    gemm_hmma<<<dim3(8, 32, 1), 256, 65536>>>(x, out, 3);
}